// round 5
// baseline (speedup 1.0000x reference)
#include <cuda_runtime.h>
#include <cstdint>

#define BTOT   65536
#define HDIM   128
#define KTOT   384
#define NG     512
#define MT     64
#define KC     32
#define NCHUNK 12
#define THREADS 512

// B pre-packed in per-warp fragment order: [ch][w16][ks4][g4][lane32][2]
__device__ float g_Bpk[NCHUNK * 16 * 16 * 64];
__device__ float g_Wz[KTOT];

#define SMEM_BYTES ((2 * 2048 + 2 * 16384) * 4)   // A: 16KB, B: 128KB

__device__ __forceinline__ uint32_t f2tf32(float x) {
    uint32_t r;
    asm("cvt.rna.tf32.f32 %0, %1;" : "=r"(r) : "f"(x));
    return r;
}
__device__ __forceinline__ uint32_t smem_u32(const void* p) {
    uint32_t a;
    asm("{ .reg .u64 t; cvta.to.shared.u64 t, %1; cvt.u32.u64 %0, t; }" : "=r"(a) : "l"(p));
    return a;
}
__device__ __forceinline__ void cp16(uint32_t dst, const void* src) {
    asm volatile("cp.async.ca.shared.global [%0], [%1], 16;" :: "r"(dst), "l"(src));
}
__device__ __forceinline__ void cp_commit() { asm volatile("cp.async.commit_group;"); }
__device__ __forceinline__ void cp_wait0()  { asm volatile("cp.async.wait_group 0;"); }

__device__ __forceinline__ float sigm(float x)     { return 1.f / (1.f + __expf(-x)); }
__device__ __forceinline__ float tanhfast(float x) { return 1.f - 2.f / (__expf(2.f * x) + 1.f); }

__device__ __forceinline__ void mma_tf32(float* d, const uint32_t* a, const uint32_t* b) {
    asm volatile(
        "mma.sync.aligned.m16n8k8.row.col.f32.tf32.tf32.f32 "
        "{%0,%1,%2,%3}, {%4,%5,%6,%7}, {%8,%9}, {%0,%1,%2,%3};"
        : "+f"(d[0]), "+f"(d[1]), "+f"(d[2]), "+f"(d[3])
        : "r"(a[0]), "r"(a[1]), "r"(a[2]), "r"(a[3]), "r"(b[0]), "r"(b[1]));
}

// ---------------------------------------------------------------------------
// Pack: [W;R;U] -> fragment-ordered, tf32-rounded B + fp32 z-column
// ---------------------------------------------------------------------------
__global__ void pack_kernel(const float* __restrict__ W, const float* __restrict__ R,
                            const float* __restrict__ U) {
    int o = blockIdx.x * blockDim.x + threadIdx.x;
    const int NB = NCHUNK * 16 * 16 * 64;
    if (o < NB) {
        int l2   = o & 63;
        int lane = l2 >> 1, half = l2 & 1;
        int gid  = lane >> 2, tig = lane & 3;
        int t  = o >> 6;
        int g  = t & 3, ks = (t >> 2) & 3, w = (t >> 4) & 15, ch = t >> 8;
        int k  = ch * KC + ks * 8 + tig + half * 4;
        int n  = g * 128 + w * 8 + gid;
        const float* src = (k < 128) ? W : (k < 256) ? R : U;
        g_Bpk[o] = __uint_as_float(f2tf32(src[(k & 127) * 513 + n]));
    } else if (o - NB < KTOT) {
        int k = o - NB;
        const float* src = (k < 128) ? W : (k < 256) ? R : U;
        g_Wz[k] = src[(k & 127) * 513 + 512];
    }
}

// ---------------------------------------------------------------------------
// Fused HMLSTM: mma.sync tf32 GEMM, cp.async-staged fragment B, exact z-dot.
// 512 threads, 64-row tile, warp w owns 8 cols (w*8..w*8+7) in each gate block.
// ---------------------------------------------------------------------------
__global__ __launch_bounds__(THREADS, 1)
void hmlstm_kernel(const float* __restrict__ hb, const float* __restrict__ hm,
                   const float* __restrict__ ht, const float* __restrict__ cm,
                   const float* __restrict__ zv, const float* __restrict__ zbv,
                   const float* __restrict__ bias, float* __restrict__ out) {
    extern __shared__ float smem[];
    float* sA = smem;            // [2][2048]
    float* sB = smem + 4096;     // [2][16384]
    const uint32_t sb_base = smem_u32(smem) + 4096u * 4u;

    const int tid  = threadIdx.x;
    const int w    = tid >> 5;
    const int lane = tid & 31;
    const int gid  = lane >> 2;
    const int tig  = lane & 3;
    const int m0   = blockIdx.x * MT;

    // loader indexing: thread -> (row lr, float4-slice lf)
    const int lr  = tid >> 3;          // 0..63
    const int lf  = tid & 7;           // 0..7
    const int lmi = lr >> 4, lgid = lr & 7, lrh = (lr >> 3) & 1;
    const int lks = lf >> 1, lkh = lf & 1;
    const int sbase = lmi * 512 + lks * 128 + lgid * 16 + lrh + 2 * lkh;

    float acc[4][4][4];
#pragma unroll
    for (int mi = 0; mi < 4; mi++)
#pragma unroll
        for (int g = 0; g < 4; g++)
#pragma unroll
            for (int q = 0; q < 4; q++) acc[mi][g][q] = 0.f;

    float4 av;
    float  zacc = 0.f;

    auto cpB = [&](int ch, int s) {
        const float* src = g_Bpk + (size_t)ch * 16384;
        uint32_t dst = sb_base + (uint32_t)s * 65536u;
#pragma unroll
        for (int it = 0; it < 8; ++it) {
            int i = it * THREADS + tid;          // 0..4095 16B chunks
            cp16(dst + (uint32_t)i * 16u, src + i * 4);
        }
    };
    auto ldgA = [&](int ch) {
        int srcid = ch >> 2, ko = (ch & 3) * KC;
        const float* x = (srcid == 0) ? hb : (srcid == 1) ? hm : ht;
        float sc = (srcid == 0) ? __ldg(zbv + m0 + lr)
                 : (srcid == 2) ? __ldg(zv + m0 + lr) : 1.f;
        float4 v = __ldg((const float4*)(x + (size_t)(m0 + lr) * HDIM + ko + lf * 4));
        v.x *= sc; v.y *= sc; v.z *= sc; v.w *= sc;
        float4 wz = __ldg((const float4*)(g_Wz + ch * KC + lf * 4));
        zacc = fmaf(v.x, wz.x, fmaf(v.y, wz.y, fmaf(v.z, wz.z, fmaf(v.w, wz.w, zacc))));
        av = v;
    };
    auto stsA = [&](int s) {
        float* A = sA + s * 2048;
        float vv[4] = {av.x, av.y, av.z, av.w};
#pragma unroll
        for (int q = 0; q < 4; q++)
            A[sbase + ((q ^ lks) & 3) * 4] = __uint_as_float(f2tf32(vv[q]));
    };
    auto ldB = [&](const float* Bp, int ks, float2* b) {
        const float2* p = (const float2*)(Bp + (w * 16 + ks * 4) * 64) + lane;
#pragma unroll
        for (int g = 0; g < 4; g++) b[g] = p[g * 32];
    };

    // prologue
    cpB(0, 0); cp_commit();
    ldgA(0); stsA(0);
    cp_wait0();
    __syncthreads();

    for (int ch = 0; ch < NCHUNK; ++ch) {
        int s = ch & 1;
        if (ch + 1 < NCHUNK) {
            cpB(ch + 1, s ^ 1); cp_commit();
            ldgA(ch + 1);
        }
        const float* A  = sA + s * 2048;
        const float* Bp = sB + s * 16384;

        float2 b0[4], b1[4];
        ldB(Bp, 0, b0);
#pragma unroll
        for (int ks = 0; ks < 4; ++ks) {
            float2* bc = (ks & 1) ? b1 : b0;
            if (ks < 3) ldB(Bp, ks + 1, (ks & 1) ? b0 : b1);
#pragma unroll
            for (int mi = 0; mi < 4; ++mi) {
                float4 a = *(const float4*)(A + mi * 512 + ks * 128 + gid * 16 +
                                            ((tig ^ ks) & 3) * 4);
                const uint32_t* au = (const uint32_t*)&a;
#pragma unroll
                for (int g = 0; g < 4; ++g)
                    mma_tf32(acc[mi][g], au, (const uint32_t*)&bc[g]);
            }
        }
        if (ch + 1 < NCHUNK) stsA(s ^ 1);
        cp_wait0();
        __syncthreads();
    }

    // ---- z_new: exact fp32 dot, threshold sz > 0 ----
    {
        float v = zacc;
        v += __shfl_xor_sync(0xffffffffu, v, 1);
        v += __shfl_xor_sync(0xffffffffu, v, 2);
        v += __shfl_xor_sync(0xffffffffu, v, 4);
        if (lf == 0)
            out[(size_t)BTOT * 2 * HDIM + m0 + lr] =
                (v + __ldg(bias + 512) > 0.f) ? 1.f : 0.f;
    }

    // ---- epilogue: gates -> h_new, c_new (sector-coalesced float2 I/O) ----
    const int j0 = w * 8 + tig * 2;
    float bi[2], bg[2], bo[2], bfv[2];
#pragma unroll
    for (int q = 0; q < 2; q++) {
        bi[q]  = __ldg(bias + j0 + q);
        bg[q]  = __ldg(bias + 128 + j0 + q);
        bo[q]  = __ldg(bias + 256 + j0 + q);
        bfv[q] = __ldg(bias + 384 + j0 + q);
    }
    float* outH = out;
    float* outC = out + (size_t)BTOT * HDIM;
#pragma unroll
    for (int mi = 0; mi < 4; ++mi) {
#pragma unroll
        for (int rh = 0; rh < 2; ++rh) {
            int r  = mi * 16 + gid + rh * 8;
            int gr = m0 + r;
            float zr_ = __ldg(zv + gr), zbr = __ldg(zbv + gr);
            bool flush = (zr_ == 1.f);
            bool copyc = (zbr == 0.f);
            bool keeph = (zr_ == 0.f) && (zbr == 0.f);
            float2 cc = __ldg((const float2*)(cm + (size_t)gr * HDIM + j0));
            float2 hh = __ldg((const float2*)(hm + (size_t)gr * HDIM + j0));
            float hn[2], cn[2];
#pragma unroll
            for (int q = 0; q < 2; ++q) {
                int reg = rh * 2 + q;
                float si = acc[mi][0][reg] + bi[q];
                float sg = acc[mi][1][reg] + bg[q];
                float so = acc[mi][2][reg] + bo[q];
                float sf = acc[mi][3][reg] + bfv[q];
                float iv = sigm(si), gv = tanhfast(sg), ov = sigm(so), fv = sigm(sf);
                float ig = iv * gv;
                float cold = q ? cc.y : cc.x;
                float cnv = flush ? ig : (copyc ? cold : fmaf(cold, fv, ig));
                float hnv = keeph ? (q ? hh.y : hh.x) : tanhfast(cnv) * ov;
                cn[q] = cnv; hn[q] = hnv;
            }
            *(float2*)(outH + (size_t)gr * HDIM + j0) = make_float2(hn[0], hn[1]);
            *(float2*)(outC + (size_t)gr * HDIM + j0) = make_float2(cn[0], cn[1]);
        }
    }
}

extern "C" void kernel_launch(void* const* d_in, const int* in_sizes, int n_in,
                              void* d_out, int out_size) {
    const float* hb = (const float*)d_in[0];
    const float* h  = (const float*)d_in[1];
    const float* ht = (const float*)d_in[2];
    const float* c  = (const float*)d_in[3];
    const float* z  = (const float*)d_in[4];
    const float* zb = (const float*)d_in[5];
    const float* W  = (const float*)d_in[6];
    const float* R  = (const float*)d_in[7];
    const float* U  = (const float*)d_in[8];
    const float* b  = (const float*)d_in[9];
    float* out = (float*)d_out;
    (void)in_sizes; (void)n_in; (void)out_size;

    int total = NCHUNK * 16 * 16 * 64 + KTOT;
    pack_kernel<<<(total + 255) / 256, 256>>>(W, R, U);

    cudaFuncSetAttribute(hmlstm_kernel,
                         cudaFuncAttributeMaxDynamicSharedMemorySize, SMEM_BYTES);
    hmlstm_kernel<<<BTOT / MT, THREADS, SMEM_BYTES>>>(hb, h, ht, c, z, zb, b, out);
}

// round 6
// speedup vs baseline: 1.3240x; 1.3240x over previous
#include <cuda_runtime.h>
#include <cuda_fp16.h>
#include <cstdint>

#define BTOT   65536
#define HDIM   128
#define KTOT   384
#define NG     512
#define MT     64
#define KC     32
#define NCHUNK 12
#define THREADS 512

// B pre-packed fp16 fragment order: [ch][w16][ks2][gp2][lane32][16B]
__device__ __half g_Bpk[NCHUNK * 16 * 2 * 2 * 32 * 8];   // 196608 halfs
__device__ float  g_Wz[KTOT];

#define SMEM_BYTES (2 * 4096 + 2 * 32768)   // A 8KB + B 64KB = 72KB

__device__ __forceinline__ uint32_t smem_u32(const void* p) {
    uint32_t a;
    asm("{ .reg .u64 t; cvta.to.shared.u64 t, %1; cvt.u32.u64 %0, t; }" : "=r"(a) : "l"(p));
    return a;
}
__device__ __forceinline__ void cp16(uint32_t dst, const void* src) {
    asm volatile("cp.async.ca.shared.global [%0], [%1], 16;" :: "r"(dst), "l"(src));
}
__device__ __forceinline__ void cp_commit() { asm volatile("cp.async.commit_group;"); }
__device__ __forceinline__ void cp_wait0()  { asm volatile("cp.async.wait_group 0;"); }

__device__ __forceinline__ float sigm(float x)     { return 1.f / (1.f + __expf(-x)); }
__device__ __forceinline__ float tanhfast(float x) { return 1.f - 2.f / (__expf(2.f * x) + 1.f); }

__device__ __forceinline__ void mma_f16(float* d, const uint32_t* a, const uint32_t* b) {
    asm volatile(
        "mma.sync.aligned.m16n8k16.row.col.f32.f16.f16.f32 "
        "{%0,%1,%2,%3}, {%4,%5,%6,%7}, {%8,%9}, {%0,%1,%2,%3};"
        : "+f"(d[0]), "+f"(d[1]), "+f"(d[2]), "+f"(d[3])
        : "r"(a[0]), "r"(a[1]), "r"(a[2]), "r"(a[3]), "r"(b[0]), "r"(b[1]));
}

// ---------------------------------------------------------------------------
// Pack: [W;R;U] -> fp16 fragment-ordered B + fp32 z-column
// B 16B unit per (ch,w,ks,gp,lane): [gA.b0(2h) gA.b1(2h) gB.b0 gB.b1]
//   b0 halfs: k = ch*32+ks*16+tig*2+{0,1}; b1: +8. n = g*128 + w*8 + gid.
// ---------------------------------------------------------------------------
__global__ void pack_kernel(const float* __restrict__ W, const float* __restrict__ R,
                            const float* __restrict__ U) {
    int o = blockIdx.x * blockDim.x + threadIdx.x;
    const int NB = NCHUNK * 16384;
    if (o < NB) {
        int h    = o & 1;
        int rsel = (o >> 1) & 1;
        int gsel = (o >> 2) & 1;
        int lane = (o >> 3) & 31;
        int gp   = (o >> 8) & 1;
        int ks   = (o >> 9) & 1;
        int w    = (o >> 10) & 15;
        int ch   = o >> 14;
        int tig = lane & 3, gid = lane >> 2;
        int k = ch * KC + ks * 16 + rsel * 8 + tig * 2 + h;
        int n = (gp * 2 + gsel) * 128 + w * 8 + gid;
        const float* src = (k < 128) ? W : (k < 256) ? R : U;
        g_Bpk[o] = __float2half_rn(src[(k & 127) * 513 + n]);
    } else if (o - NB < KTOT) {
        int k = o - NB;
        const float* src = (k < 128) ? W : (k < 256) ? R : U;
        g_Wz[k] = src[(k & 127) * 513 + 512];
    }
}

// ---------------------------------------------------------------------------
// Fused HMLSTM: fp16 m16n8k16 mma.sync GEMM (fp32 accum) + exact fp32 z-dot.
// 512 threads, 64-row tile, warp w owns 8 cols (w*8..) in each gate block.
// ---------------------------------------------------------------------------
__global__ __launch_bounds__(THREADS, 1)
void hmlstm_kernel(const float* __restrict__ hb, const float* __restrict__ hm,
                   const float* __restrict__ ht, const float* __restrict__ cm,
                   const float* __restrict__ zv, const float* __restrict__ zbv,
                   const float* __restrict__ bias, float* __restrict__ out) {
    extern __shared__ char smem[];
    char* sAc = smem;            // [2][4096B]  A fragments (fp16)
    char* sBc = smem + 8192;     // [2][32768B] B fragments (fp16)
    const uint32_t sb_base = smem_u32(smem) + 8192u;

    const int tid  = threadIdx.x;
    const int w    = tid >> 5;
    const int lane = tid & 31;
    const int gid  = lane >> 2;
    const int tig  = lane & 3;
    const int m0   = blockIdx.x * MT;

    // loader indexing: thread -> (row lr, float4-slice lf)
    const int lr = tid >> 3;           // 0..63
    const int lf = tid & 7;            // 0..7 (k = lf*4 .. +3 within chunk)
    const int lmi = lr >> 4, lgid = lr & 7, lrh = (lr >> 3) & 1;
    const int lks = lf >> 2, lkh = (lf >> 1) & 1, ltg = (lf & 1) * 2;
    // byte offset of this thread's first half2 within an A stage
    const int abase = ((lmi * 2 + lks) * 32 + lgid * 4 + ltg) * 16 + (lkh * 2 + lrh) * 4;

    float acc[4][4][4];
#pragma unroll
    for (int mi = 0; mi < 4; mi++)
#pragma unroll
        for (int g = 0; g < 4; g++)
#pragma unroll
            for (int q = 0; q < 4; q++) acc[mi][g][q] = 0.f;

    float4 av;
    float  zacc = 0.f;

    auto cpB = [&](int ch, int s) {
        const __half* src = g_Bpk + (size_t)ch * 16384;
        uint32_t dst = sb_base + (uint32_t)s * 32768u;
#pragma unroll
        for (int it = 0; it < 4; ++it) {
            int i = it * THREADS + tid;          // 0..2047 16B units
            cp16(dst + (uint32_t)i * 16u, src + i * 8);
        }
    };
    auto ldgA = [&](int ch) {
        int srcid = ch >> 2, ko = (ch & 3) * KC;
        const float* x = (srcid == 0) ? hb : (srcid == 1) ? hm : ht;
        float sc = (srcid == 0) ? __ldg(zbv + m0 + lr)
                 : (srcid == 2) ? __ldg(zv + m0 + lr) : 1.f;
        float4 v = __ldg((const float4*)(x + (size_t)(m0 + lr) * HDIM + ko + lf * 4));
        v.x *= sc; v.y *= sc; v.z *= sc; v.w *= sc;
        float4 wz = __ldg((const float4*)(g_Wz + ch * KC + lf * 4));
        zacc = fmaf(v.x, wz.x, fmaf(v.y, wz.y, fmaf(v.z, wz.z, fmaf(v.w, wz.w, zacc))));
        av = v;
    };
    auto stsA = [&](int s) {
        char* A = sAc + s * 4096;
        *(__half2*)(A + abase)      = __floats2half2_rn(av.x, av.y);
        *(__half2*)(A + abase + 16) = __floats2half2_rn(av.z, av.w);
    };

    // prologue
    cpB(0, 0); cp_commit();
    ldgA(0); stsA(0);
    cp_wait0();
    __syncthreads();

    for (int ch = 0; ch < NCHUNK; ++ch) {
        int s = ch & 1;
        if (ch + 1 < NCHUNK) {
            cpB(ch + 1, s ^ 1); cp_commit();
            ldgA(ch + 1);
        }
        const char* A  = sAc + s * 4096;
        const char* Bp = sBc + s * 32768;

        // preload both k-steps' B fragments (4 LDS.128)
        uint4 bfrag[2][2];
#pragma unroll
        for (int ks = 0; ks < 2; ++ks)
#pragma unroll
            for (int gp = 0; gp < 2; ++gp)
                bfrag[ks][gp] = *(const uint4*)(Bp + (((w * 2 + ks) * 2 + gp) * 32 + lane) * 16);

#pragma unroll
        for (int ks = 0; ks < 2; ++ks) {
#pragma unroll
            for (int mi = 0; mi < 4; ++mi) {
                uint4 a = *(const uint4*)(A + ((mi * 2 + ks) * 32 + lane) * 16);
                const uint32_t* au = (const uint32_t*)&a;
                const uint32_t* b0 = (const uint32_t*)&bfrag[ks][0];
                const uint32_t* b1 = (const uint32_t*)&bfrag[ks][1];
                mma_f16(acc[mi][0], au, b0 + 0);
                mma_f16(acc[mi][1], au, b0 + 2);
                mma_f16(acc[mi][2], au, b1 + 0);
                mma_f16(acc[mi][3], au, b1 + 2);
            }
        }
        if (ch + 1 < NCHUNK) stsA(s ^ 1);
        cp_wait0();
        __syncthreads();
    }

    // ---- z_new: exact fp32 dot, threshold sz > 0 ----
    {
        float v = zacc;
        v += __shfl_xor_sync(0xffffffffu, v, 1);
        v += __shfl_xor_sync(0xffffffffu, v, 2);
        v += __shfl_xor_sync(0xffffffffu, v, 4);
        if (lf == 0)
            out[(size_t)BTOT * 2 * HDIM + m0 + lr] =
                (v + __ldg(bias + 512) > 0.f) ? 1.f : 0.f;
    }

    // ---- epilogue: gates -> h_new, c_new (sector-coalesced float2 I/O) ----
    const int j0 = w * 8 + tig * 2;
    float bi[2], bg[2], bo[2], bfv[2];
#pragma unroll
    for (int q = 0; q < 2; q++) {
        bi[q]  = __ldg(bias + j0 + q);
        bg[q]  = __ldg(bias + 128 + j0 + q);
        bo[q]  = __ldg(bias + 256 + j0 + q);
        bfv[q] = __ldg(bias + 384 + j0 + q);
    }
    float* outH = out;
    float* outC = out + (size_t)BTOT * HDIM;
#pragma unroll
    for (int mi = 0; mi < 4; ++mi) {
#pragma unroll
        for (int rh = 0; rh < 2; ++rh) {
            int r  = mi * 16 + gid + rh * 8;
            int gr = m0 + r;
            float zr_ = __ldg(zv + gr), zbr = __ldg(zbv + gr);
            bool flush = (zr_ == 1.f);
            bool copyc = (zbr == 0.f);
            bool keeph = (zr_ == 0.f) && (zbr == 0.f);
            float2 cc = __ldg((const float2*)(cm + (size_t)gr * HDIM + j0));
            float2 hh = __ldg((const float2*)(hm + (size_t)gr * HDIM + j0));
            float hn[2], cn[2];
#pragma unroll
            for (int q = 0; q < 2; ++q) {
                int reg = rh * 2 + q;
                float si = acc[mi][0][reg] + bi[q];
                float sg = acc[mi][1][reg] + bg[q];
                float so = acc[mi][2][reg] + bo[q];
                float sf = acc[mi][3][reg] + bfv[q];
                float iv = sigm(si), gv = tanhfast(sg), ov = sigm(so), fv = sigm(sf);
                float ig = iv * gv;
                float cold = q ? cc.y : cc.x;
                float cnv = flush ? ig : (copyc ? cold : fmaf(cold, fv, ig));
                float hnv = keeph ? (q ? hh.y : hh.x) : tanhfast(cnv) * ov;
                cn[q] = cnv; hn[q] = hnv;
            }
            *(float2*)(outH + (size_t)gr * HDIM + j0) = make_float2(hn[0], hn[1]);
            *(float2*)(outC + (size_t)gr * HDIM + j0) = make_float2(cn[0], cn[1]);
        }
    }
}

extern "C" void kernel_launch(void* const* d_in, const int* in_sizes, int n_in,
                              void* d_out, int out_size) {
    const float* hb = (const float*)d_in[0];
    const float* h  = (const float*)d_in[1];
    const float* ht = (const float*)d_in[2];
    const float* c  = (const float*)d_in[3];
    const float* z  = (const float*)d_in[4];
    const float* zb = (const float*)d_in[5];
    const float* W  = (const float*)d_in[6];
    const float* R  = (const float*)d_in[7];
    const float* U  = (const float*)d_in[8];
    const float* b  = (const float*)d_in[9];
    float* out = (float*)d_out;
    (void)in_sizes; (void)n_in; (void)out_size;

    int total = NCHUNK * 16384 + KTOT;
    pack_kernel<<<(total + 255) / 256, 256>>>(W, R, U);

    cudaFuncSetAttribute(hmlstm_kernel,
                         cudaFuncAttributeMaxDynamicSharedMemorySize, SMEM_BYTES);
    hmlstm_kernel<<<BTOT / MT, THREADS, SMEM_BYTES>>>(hb, h, ht, c, z, zb, b, out);
}

// round 7
// speedup vs baseline: 1.3695x; 1.0344x over previous
#include <cuda_runtime.h>
#include <cuda_fp16.h>
#include <cstdint>

#define BTOT   65536
#define HDIM   128
#define KTOT   384
#define NG     512
#define MT     64
#define KC     32
#define NCHUNK 12
#define THREADS 1024

// B pre-packed fp16 fragment order: [ch][w16][ks2][gp2][lane32][16B]
__device__ __half g_Bpk[NCHUNK * 16 * 2 * 2 * 32 * 8];   // 196608 halfs
__device__ float  g_Wz[KTOT];

#define A_STAGE_B 4096
#define B_STAGE_B 32768
#define SMEM_BYTES (2 * A_STAGE_B + 3 * B_STAGE_B)   // 8KB + 96KB = 104KB

__device__ __forceinline__ uint32_t smem_u32(const void* p) {
    uint32_t a;
    asm("{ .reg .u64 t; cvta.to.shared.u64 t, %1; cvt.u32.u64 %0, t; }" : "=r"(a) : "l"(p));
    return a;
}
__device__ __forceinline__ void cp16(uint32_t dst, const void* src) {
    asm volatile("cp.async.ca.shared.global [%0], [%1], 16;" :: "r"(dst), "l"(src));
}
__device__ __forceinline__ void cp_commit() { asm volatile("cp.async.commit_group;"); }
__device__ __forceinline__ void cp_wait1()  { asm volatile("cp.async.wait_group 1;"); }

__device__ __forceinline__ float sigm(float x)     { return 1.f / (1.f + __expf(-x)); }
__device__ __forceinline__ float tanhfast(float x) { return 1.f - 2.f / (__expf(2.f * x) + 1.f); }

__device__ __forceinline__ void mma_f16(float* d, const uint32_t* a, const uint32_t* b) {
    asm volatile(
        "mma.sync.aligned.m16n8k16.row.col.f32.f16.f16.f32 "
        "{%0,%1,%2,%3}, {%4,%5,%6,%7}, {%8,%9}, {%0,%1,%2,%3};"
        : "+f"(d[0]), "+f"(d[1]), "+f"(d[2]), "+f"(d[3])
        : "r"(a[0]), "r"(a[1]), "r"(a[2]), "r"(a[3]), "r"(b[0]), "r"(b[1]));
}

// ---------------------------------------------------------------------------
// Pack: [W;R;U] -> fp16 fragment-ordered B + fp32 z-column (same as R6)
// ---------------------------------------------------------------------------
__global__ void pack_kernel(const float* __restrict__ W, const float* __restrict__ R,
                            const float* __restrict__ U) {
    int o = blockIdx.x * blockDim.x + threadIdx.x;
    const int NB = NCHUNK * 16384;
    if (o < NB) {
        int h    = o & 1;
        int rsel = (o >> 1) & 1;
        int gsel = (o >> 2) & 1;
        int lane = (o >> 3) & 31;
        int gp   = (o >> 8) & 1;
        int ks   = (o >> 9) & 1;
        int w    = (o >> 10) & 15;
        int ch   = o >> 14;
        int tig = lane & 3, gid = lane >> 2;
        int k = ch * KC + ks * 16 + rsel * 8 + tig * 2 + h;
        int n = (gp * 2 + gsel) * 128 + w * 8 + gid;
        const float* src = (k < 128) ? W : (k < 256) ? R : U;
        g_Bpk[o] = __float2half_rn(src[(k & 127) * 513 + n]);
    } else if (o - NB < KTOT) {
        int k = o - NB;
        const float* src = (k < 128) ? W : (k < 256) ? R : U;
        g_Wz[k] = src[(k & 127) * 513 + 512];
    }
}

// ---------------------------------------------------------------------------
// Fused HMLSTM: fp16 m16n8k16 mma.sync (fp32 accum), 1024 thr, 3-stage B pipe.
// Warp w: rows (w>>4)*32..+31, cols (w&15)*8 replicated across 4 gate blocks.
// ---------------------------------------------------------------------------
__global__ __launch_bounds__(THREADS, 1)
void hmlstm_kernel(const float* __restrict__ hb, const float* __restrict__ hm,
                   const float* __restrict__ ht, const float* __restrict__ cm,
                   const float* __restrict__ zv, const float* __restrict__ zbv,
                   const float* __restrict__ bias, float* __restrict__ out) {
    extern __shared__ char smem[];
    char* sAc = smem;                        // [2][4096B]
    char* sBc = smem + 2 * A_STAGE_B;        // [3][32768B]
    const uint32_t sb_base = smem_u32(smem) + 2u * A_STAGE_B;

    const int tid  = threadIdx.x;
    const int w    = tid >> 5;
    const int lane = tid & 31;
    const int gid  = lane >> 2;
    const int tig  = lane & 3;
    const int wq   = w & 15;      // col group
    const int mh   = w >> 4;      // row half
    const int m0   = blockIdx.x * MT;

    // loader indexing: thread -> (row lr 0..63, k-pair c2 0..15)
    const int lr = tid >> 4;
    const int c2 = tid & 15;
    const int lmi = lr >> 4, lg8 = lr & 7, lrh = (lr >> 3) & 1;
    const int lks = c2 >> 3, lkh = (c2 >> 2) & 1, ltg = c2 & 3;
    const int abase = ((lmi * 2 + lks) * 32 + lg8 * 4 + ltg) * 16 + (lkh * 2 + lrh) * 4;

    float acc[2][4][4];
#pragma unroll
    for (int q = 0; q < 2; q++)
#pragma unroll
        for (int g = 0; g < 4; g++)
#pragma unroll
            for (int r = 0; r < 4; r++) acc[q][g][r] = 0.f;

    float2 av;
    float  zacc = 0.f;

    auto cpB = [&](int ch, int s) {
        const __half* src = g_Bpk + (size_t)ch * 16384;
        uint32_t dst = sb_base + (uint32_t)s * B_STAGE_B;
#pragma unroll
        for (int it = 0; it < 2; ++it) {
            int i = it * THREADS + tid;          // 0..2047 16B units
            cp16(dst + (uint32_t)i * 16u, src + i * 8);
        }
    };
    auto ldgA = [&](int ch) {
        int srcid = ch >> 2, ko = (ch & 3) * KC;
        const float* x = (srcid == 0) ? hb : (srcid == 1) ? hm : ht;
        float sc = (srcid == 0) ? __ldg(zbv + m0 + lr)
                 : (srcid == 2) ? __ldg(zv + m0 + lr) : 1.f;
        float2 v = __ldg((const float2*)(x + (size_t)(m0 + lr) * HDIM + ko + c2 * 2));
        v.x *= sc; v.y *= sc;
        float2 wz = __ldg((const float2*)(g_Wz + ch * KC + c2 * 2));
        zacc = fmaf(v.x, wz.x, fmaf(v.y, wz.y, zacc));
        av = v;
    };
    auto stsA = [&](int s) {
        *(__half2*)(sAc + s * A_STAGE_B + abase) = __floats2half2_rn(av.x, av.y);
    };

    // prologue: B0, B1 in flight; A0 staged
    cpB(0, 0); cp_commit();
    cpB(1, 1); cp_commit();
    ldgA(0); stsA(0);
    cp_wait1();                 // B0 done, B1 in flight
    __syncthreads();

    for (int ch = 0; ch < NCHUNK; ++ch) {
        int sB = ch % 3;
        int sA = ch & 1;
        if (ch + 2 < NCHUNK) cpB(ch + 2, (ch + 2) % 3);
        cp_commit();            // always commit (empty group near tail)
        if (ch + 1 < NCHUNK) ldgA(ch + 1);

        const char* A  = sAc + sA * A_STAGE_B;
        const char* Bp = sBc + sB * B_STAGE_B;

#pragma unroll
        for (int ks = 0; ks < 2; ++ks) {
            uint4 b0 = *(const uint4*)(Bp + (((wq * 2 + ks) * 2 + 0) * 32 + lane) * 16);
            uint4 b1 = *(const uint4*)(Bp + (((wq * 2 + ks) * 2 + 1) * 32 + lane) * 16);
#pragma unroll
            for (int q = 0; q < 2; ++q) {
                int mi = mh * 2 + q;
                uint4 a = *(const uint4*)(A + ((mi * 2 + ks) * 32 + lane) * 16);
                const uint32_t* au = (const uint32_t*)&a;
                mma_f16(acc[q][0], au, (const uint32_t*)&b0 + 0);
                mma_f16(acc[q][1], au, (const uint32_t*)&b0 + 2);
                mma_f16(acc[q][2], au, (const uint32_t*)&b1 + 0);
                mma_f16(acc[q][3], au, (const uint32_t*)&b1 + 2);
            }
        }
        if (ch + 1 < NCHUNK) stsA(sA ^ 1);
        cp_wait1();             // B(ch+1) arrived; B(ch+2) may be in flight
        __syncthreads();
    }

    // ---- z_new: exact fp32 dot over 16 threads/row, threshold sz > 0 ----
    {
        float v = zacc;
        v += __shfl_xor_sync(0xffffffffu, v, 1);
        v += __shfl_xor_sync(0xffffffffu, v, 2);
        v += __shfl_xor_sync(0xffffffffu, v, 4);
        v += __shfl_xor_sync(0xffffffffu, v, 8);
        if (c2 == 0)
            out[(size_t)BTOT * 2 * HDIM + m0 + lr] =
                (v + __ldg(bias + 512) > 0.f) ? 1.f : 0.f;
    }

    // ---- epilogue: gates -> h_new, c_new (sector-coalesced float2 I/O) ----
    const int j0 = wq * 8 + tig * 2;
    float bi[2], bg[2], bo[2], bfv[2];
#pragma unroll
    for (int q = 0; q < 2; q++) {
        bi[q]  = __ldg(bias + j0 + q);
        bg[q]  = __ldg(bias + 128 + j0 + q);
        bo[q]  = __ldg(bias + 256 + j0 + q);
        bfv[q] = __ldg(bias + 384 + j0 + q);
    }
    float* outH = out;
    float* outC = out + (size_t)BTOT * HDIM;
#pragma unroll
    for (int q = 0; q < 2; ++q) {
        int mi = mh * 2 + q;
#pragma unroll
        for (int rh = 0; rh < 2; ++rh) {
            int r  = mi * 16 + gid + rh * 8;
            int gr = m0 + r;
            float zr_ = __ldg(zv + gr), zbr = __ldg(zbv + gr);
            bool flush = (zr_ == 1.f);
            bool copyc = (zbr == 0.f);
            bool keeph = (zr_ == 0.f) && (zbr == 0.f);
            float2 cc = __ldg((const float2*)(cm + (size_t)gr * HDIM + j0));
            float2 hh = __ldg((const float2*)(hm + (size_t)gr * HDIM + j0));
            float hn[2], cn[2];
#pragma unroll
            for (int p = 0; p < 2; ++p) {
                int reg = rh * 2 + p;
                float si = acc[q][0][reg] + bi[p];
                float sg = acc[q][1][reg] + bg[p];
                float so = acc[q][2][reg] + bo[p];
                float sf = acc[q][3][reg] + bfv[p];
                float iv = sigm(si), gv = tanhfast(sg), ov = sigm(so), fv = sigm(sf);
                float ig = iv * gv;
                float cold = p ? cc.y : cc.x;
                float cnv = flush ? ig : (copyc ? cold : fmaf(cold, fv, ig));
                float hnv = keeph ? (p ? hh.y : hh.x) : tanhfast(cnv) * ov;
                cn[p] = cnv; hn[p] = hnv;
            }
            *(float2*)(outH + (size_t)gr * HDIM + j0) = make_float2(hn[0], hn[1]);
            *(float2*)(outC + (size_t)gr * HDIM + j0) = make_float2(cn[0], cn[1]);
        }
    }
}

extern "C" void kernel_launch(void* const* d_in, const int* in_sizes, int n_in,
                              void* d_out, int out_size) {
    const float* hb = (const float*)d_in[0];
    const float* h  = (const float*)d_in[1];
    const float* ht = (const float*)d_in[2];
    const float* c  = (const float*)d_in[3];
    const float* z  = (const float*)d_in[4];
    const float* zb = (const float*)d_in[5];
    const float* W  = (const float*)d_in[6];
    const float* R  = (const float*)d_in[7];
    const float* U  = (const float*)d_in[8];
    const float* b  = (const float*)d_in[9];
    float* out = (float*)d_out;
    (void)in_sizes; (void)n_in; (void)out_size;

    int total = NCHUNK * 16384 + KTOT;
    pack_kernel<<<(total + 255) / 256, 256>>>(W, R, U);

    cudaFuncSetAttribute(hmlstm_kernel,
                         cudaFuncAttributeMaxDynamicSharedMemorySize, SMEM_BYTES);
    hmlstm_kernel<<<BTOT / MT, THREADS, SMEM_BYTES>>>(hb, h, ht, c, z, zb, b, out);
}